// round 10
// baseline (speedup 1.0000x reference)
#include <cuda_runtime.h>

#define TPB    256
#define WARPS  (TPB / 32)
#define PLANE  199                  // plane stride: > f(191)=196, odd
#define WSMEM  (3 * PLANE)          // 3 component planes per warp

// Global double accumulator. Zero at load; finalize_kernel resets it after
// consuming, so every launch / graph replay starts from 0.
__device__ double g_accum;

__device__ __forceinline__ float4 ldcs_f4(const float4* p) {
    float4 v;
    asm volatile("ld.global.cs.v4.f32 {%0,%1,%2,%3}, [%4];"
                 : "=f"(v.x), "=f"(v.y), "=f"(v.z), "=f"(v.w)
                 : "l"(p));
    return v;
}

__global__ void __launch_bounds__(TPB) loss_kernel(const float4* __restrict__ in,
                                                   int nrows) {
    __shared__ float s[WARPS * WSMEM];

    const int tid  = threadIdx.x;
    const int lane = tid & 31;
    const int w    = tid >> 5;
    const int warp_row0 = blockIdx.x * TPB + w * 32;

    float acc = 0.0f;

    if (warp_row0 + 32 <= nrows) {
        // ---- 1) Coalesced streaming load: 32 rows = 3072 contiguous bytes ----
        const float4* __restrict__ g4 = in + (size_t)warp_row0 * 6;
        float4 v[6];
        #pragma unroll
        for (int i = 0; i < 6; i++)
            v[i] = ldcs_f4(g4 + i * 32 + lane);

        // ---- 2) Normalize in registers (each float4 = one 3-vector y,z,w) ----
        float nx[6], ny[6], nz[6];
        #pragma unroll
        for (int i = 0; i < 6; i++) {
            float x = v[i].y, y = v[i].z, z = v[i].w;
            float inv = rsqrtf(x * x + y * y + z * z);
            nx[i] = x * inv; ny[i] = y * inv; nz[i] = z * inv;
        }

        // ---- 3) Plane-major smem store, skew f(k)=k+(k>>5) ----
        float* sw = s + w * WSMEM;
        #pragma unroll
        for (int i = 0; i < 6; i++) {
            int fi = 33 * i + lane;
            sw[0 * PLANE + fi] = nx[i];
            sw[1 * PLANE + fi] = ny[i];
            sw[2 * PLANE + fi] = nz[i];
        }
        __syncwarp();

        // ---- 4) Gather own row (local row = lane) ----
        float ax[6], ay[6], az[6];
        #pragma unroll
        for (int j = 0; j < 6; j++) {
            int m  = 6 * lane + j;
            int fm = m + (m >> 5);
            ax[j] = sw[0 * PLANE + fm];
            ay[j] = sw[1 * PLANE + fm];
            az[j] = sw[2 * PLANE + fm];
        }

        // Off-diagonal Gram terms only (diag ~1e-13 relative, dropped).
        #pragma unroll
        for (int g = 0; g < 2; g++) {
            int b = 3 * g;
            float dab = ax[b]   * ax[b+1] + ay[b]   * ay[b+1] + az[b]   * az[b+1];
            float dac = ax[b]   * ax[b+2] + ay[b]   * ay[b+2] + az[b]   * az[b+2];
            float dbc = ax[b+1] * ax[b+2] + ay[b+1] * ay[b+2] + az[b+1] * az[b+2];
            acc += 2.0f * (dab * dab + dac * dac + dbc * dbc);
        }
    } else {
        // ---- Tail (partial warp): direct per-row loads ----
        int row = warp_row0 + lane;
        if (row < nrows) {
            const float4* __restrict__ rp = in + (size_t)row * 6;
            #pragma unroll
            for (int g = 0; g < 2; g++) {
                float4 p = rp[3*g], q = rp[3*g+1], r = rp[3*g+2];
                float ia = rsqrtf(p.y*p.y + p.z*p.z + p.w*p.w);
                float ib = rsqrtf(q.y*q.y + q.z*q.z + q.w*q.w);
                float ic = rsqrtf(r.y*r.y + r.z*r.z + r.w*r.w);
                float a0 = p.y*ia, a1 = p.z*ia, a2 = p.w*ia;
                float b0 = q.y*ib, b1 = q.z*ib, b2 = q.w*ib;
                float c0 = r.y*ic, c1 = r.z*ic, c2 = r.w*ic;
                float dab = a0*b0 + a1*b1 + a2*b2;
                float dac = a0*c0 + a1*c1 + a2*c2;
                float dbc = b0*c0 + b1*c1 + b2*c2;
                acc += 2.0f * (dab*dab + dac*dac + dbc*dbc);
            }
        }
    }

    // ---- Block reduction ----
    #pragma unroll
    for (int off = 16; off > 0; off >>= 1)
        acc += __shfl_xor_sync(0xFFFFFFFFu, acc, off);

    __shared__ float ws[WARPS];
    if (lane == 0) ws[w] = acc;
    __syncthreads();

    if (w == 0) {
        acc = (lane < WARPS) ? ws[lane] : 0.0f;
        #pragma unroll
        for (int off = 4; off > 0; off >>= 1)
            acc += __shfl_xor_sync(0xFFFFFFFFu, acc, off);
        if (lane == 0)
            atomicAdd(&g_accum, (double)acc);  // REDG, no-return
    }
}

__global__ void finalize_kernel(float* out, int nrows) {
    // PDL: this kernel may be launched while loss_kernel is still draining.
    // Block until the primary grid's memory ops (all REDGs) are visible.
    cudaGridDependencySynchronize();
    out[0] = (float)(g_accum / (double)nrows);
    g_accum = 0.0;  // reset for next launch / graph replay
}

extern "C" void kernel_launch(void* const* d_in, const int* in_sizes, int n_in,
                              void* d_out, int out_size) {
    const float4* in = (const float4*)d_in[0];
    float* out = (float*)d_out;
    int nrows = in_sizes[0] / 24;  // 24 floats per row
    int blocks = (nrows + TPB - 1) / TPB;

    loss_kernel<<<blocks, TPB>>>(in, nrows);

    // Programmatic dependent launch: overlap finalize's launch latency with
    // the tail of loss_kernel. cudaGridDependencySynchronize() inside
    // finalize provides the ordering the stream dependency used to.
    cudaLaunchConfig_t cfg = {};
    cfg.gridDim  = dim3(1, 1, 1);
    cfg.blockDim = dim3(1, 1, 1);
    cudaLaunchAttribute attrs[1];
    attrs[0].id = cudaLaunchAttributeProgrammaticStreamSerialization;
    attrs[0].val.programmaticStreamSerializationAllowed = 1;
    cfg.attrs = attrs;
    cfg.numAttrs = 1;
    cudaLaunchKernelEx(&cfg, finalize_kernel, out, nrows);
}

// round 11
// speedup vs baseline: 1.0047x; 1.0047x over previous
#include <cuda_runtime.h>

#define TPB     256
#define WARPS   (TPB / 32)
#define RPW     64                   // rows per warp
#define PLANE   397                  // > f(383)=394, odd
#define WSMEM   (3 * PLANE)          // 3 component planes per warp

// Global double accumulator. Zero at load; finalize_kernel resets it after
// consuming, so every launch / graph replay starts from 0.
__device__ double g_accum;

__device__ __forceinline__ float4 ldcs_f4(const float4* p) {
    float4 v;
    asm volatile("ld.global.cs.v4.f32 {%0,%1,%2,%3}, [%4];"
                 : "=f"(v.x), "=f"(v.y), "=f"(v.z), "=f"(v.w)
                 : "l"(p));
    return v;
}

__device__ __forceinline__ float row_loss(const float* sw, int row) {
    float ax[6], ay[6], az[6];
    #pragma unroll
    for (int j = 0; j < 6; j++) {
        int m  = 6 * row + j;
        int fm = m + (m >> 5);
        ax[j] = sw[0 * PLANE + fm];
        ay[j] = sw[1 * PLANE + fm];
        az[j] = sw[2 * PLANE + fm];
    }
    float acc = 0.0f;
    #pragma unroll
    for (int g = 0; g < 2; g++) {
        int b = 3 * g;
        float dab = ax[b]   * ax[b+1] + ay[b]   * ay[b+1] + az[b]   * az[b+1];
        float dac = ax[b]   * ax[b+2] + ay[b]   * ay[b+2] + az[b]   * az[b+2];
        float dbc = ax[b+1] * ax[b+2] + ay[b+1] * ay[b+2] + az[b+1] * az[b+2];
        acc += 2.0f * (dab * dab + dac * dac + dbc * dbc);
    }
    return acc;
}

__global__ void __launch_bounds__(TPB) loss_kernel(const float4* __restrict__ in,
                                                   int nrows) {
    __shared__ float s[WARPS * WSMEM];   // 38112 B

    const int tid  = threadIdx.x;
    const int lane = tid & 31;
    const int w    = tid >> 5;
    const int warp_row0 = (blockIdx.x * WARPS + w) * RPW;

    float acc = 0.0f;

    if (warp_row0 + RPW <= nrows) {
        // ---- 1) 12 front-batched coalesced LDG.128 (64 rows = 6144 B) ----
        const float4* __restrict__ g4 = in + (size_t)warp_row0 * 6;
        float4 v[12];
        #pragma unroll
        for (int i = 0; i < 12; i++)
            v[i] = ldcs_f4(g4 + i * 32 + lane);

        // ---- 2+3) Normalize in registers, store to skewed planes ----
        // k = 32*i + lane -> f(k) = 33*i + lane: lane-consecutive, conflict-free.
        float* sw = s + w * WSMEM;
        #pragma unroll
        for (int i = 0; i < 12; i++) {
            float x = v[i].y, y = v[i].z, z = v[i].w;
            float inv = rsqrtf(x * x + y * y + z * z);
            int fi = 33 * i + lane;
            sw[0 * PLANE + fi] = x * inv;
            sw[1 * PLANE + fi] = y * inv;
            sw[2 * PLANE + fi] = z * inv;
        }
        __syncwarp();

        // ---- 4) Each thread computes two rows: lane and lane+32 ----
        acc  = row_loss(sw, lane);
        acc += row_loss(sw, lane + 32);
    } else {
        // ---- Tail: direct per-row loads, two rows per thread ----
        #pragma unroll
        for (int t = 0; t < 2; t++) {
            int row = warp_row0 + lane + t * 32;
            if (row < nrows) {
                const float4* __restrict__ rp = in + (size_t)row * 6;
                #pragma unroll
                for (int g = 0; g < 2; g++) {
                    float4 p = rp[3*g], q = rp[3*g+1], r = rp[3*g+2];
                    float ia = rsqrtf(p.y*p.y + p.z*p.z + p.w*p.w);
                    float ib = rsqrtf(q.y*q.y + q.z*q.z + q.w*q.w);
                    float ic = rsqrtf(r.y*r.y + r.z*r.z + r.w*r.w);
                    float a0 = p.y*ia, a1 = p.z*ia, a2 = p.w*ia;
                    float b0 = q.y*ib, b1 = q.z*ib, b2 = q.w*ib;
                    float c0 = r.y*ic, c1 = r.z*ic, c2 = r.w*ic;
                    float dab = a0*b0 + a1*b1 + a2*b2;
                    float dac = a0*c0 + a1*c1 + a2*c2;
                    float dbc = b0*c0 + b1*c1 + b2*c2;
                    acc += 2.0f * (dab*dab + dac*dac + dbc*dbc);
                }
            }
        }
    }

    // ---- Block reduction ----
    #pragma unroll
    for (int off = 16; off > 0; off >>= 1)
        acc += __shfl_xor_sync(0xFFFFFFFFu, acc, off);

    __shared__ float ws[WARPS];
    if (lane == 0) ws[w] = acc;
    __syncthreads();

    if (w == 0) {
        acc = (lane < WARPS) ? ws[lane] : 0.0f;
        #pragma unroll
        for (int off = 4; off > 0; off >>= 1)
            acc += __shfl_xor_sync(0xFFFFFFFFu, acc, off);
        if (lane == 0) {
            atomicAdd(&g_accum, (double)acc);  // REDG, no-return
            // PDL: signal this CTA's contribution is visible; lets the
            // dependent finalize release as the grid drains.
            cudaTriggerProgrammaticLaunchCompletion();
        }
    }
}

__global__ void finalize_kernel(float* out, int nrows) {
    // Block until the primary grid's memory ops (all REDGs) are visible.
    cudaGridDependencySynchronize();
    out[0] = (float)(g_accum / (double)nrows);
    g_accum = 0.0;  // reset for next launch / graph replay
}

extern "C" void kernel_launch(void* const* d_in, const int* in_sizes, int n_in,
                              void* d_out, int out_size) {
    const float4* in = (const float4*)d_in[0];
    float* out = (float*)d_out;
    int nrows = in_sizes[0] / 24;  // 24 floats per row
    int rows_per_block = WARPS * RPW;   // 512
    int blocks = (nrows + rows_per_block - 1) / rows_per_block;

    loss_kernel<<<blocks, TPB>>>(in, nrows);

    cudaLaunchConfig_t cfg = {};
    cfg.gridDim  = dim3(1, 1, 1);
    cfg.blockDim = dim3(1, 1, 1);
    cudaLaunchAttribute attrs[1];
    attrs[0].id = cudaLaunchAttributeProgrammaticStreamSerialization;
    attrs[0].val.programmaticStreamSerializationAllowed = 1;
    cfg.attrs = attrs;
    cfg.numAttrs = 1;
    cudaLaunchKernelEx(&cfg, finalize_kernel, out, nrows);
}